// round 10
// baseline (speedup 1.0000x reference)
#include <cuda_runtime.h>
#include <cstdint>

#define CDIM    64
#define KCODES  1024
#define HWDIM   1024
#define BM      128
#define BN      64                  // codes per chunk
#define NCHUNK  (KCODES / BN)
#define NBLOCKS (65536 / BM)

#define STX     132                 // s_x row stride (floats)
#define STB     68                  // s_b row stride (floats)

// dynamic smem layout (float offsets)
#define SF_X    0                                   // 64*132 = 8448
#define SF_BH   (64 * STX)                          // 4352
#define SF_BL   (SF_BH + 64 * STB)
#define SF_HN   (SF_BL + 64 * STB)                  // 1024
#define SF_C1   (SF_HN + KCODES)                    // 128 ints
#define SF_C2   (SF_C1 + 128)                       // 128 ints
#define SF_RS   (SF_C2 + 128)                       // 256 floats
#define SF_FIN  (SF_RS + 256)                       // 128 ints
#define SF_TOT  (SF_FIN + 128)
#define SMEM_BYTES (SF_TOT * 4)                     // 75264 B

__device__ float d_hn[KCODES];      // 0.5*||c_k||^2

__global__ void hn_kernel(const float* __restrict__ cb) {
    int k = blockIdx.x * blockDim.x + threadIdx.x;
    if (k < KCODES) {
        const float4* row = reinterpret_cast<const float4*>(cb + k * CDIM);
        float s = 0.f;
        #pragma unroll
        for (int i = 0; i < CDIM / 4; ++i) {
            float4 v = __ldg(&row[i]);
            s += v.x * v.x + v.y * v.y + v.z * v.z + v.w * v.w;
        }
        d_hn[k] = 0.5f * s;
    }
}

// m16n8k8 tf32 MMA (baseline PTX, sm_80+): D += A*B, fp32 accumulate
static __forceinline__ __device__ void mma8(float* c, uint32_t a0, uint32_t a1,
                                            uint32_t a2, uint32_t a3,
                                            uint32_t b0, uint32_t b1) {
    asm("mma.sync.aligned.m16n8k8.row.col.f32.tf32.tf32.f32 "
        "{%0,%1,%2,%3}, {%4,%5,%6,%7}, {%8,%9}, {%0,%1,%2,%3};"
        : "+f"(c[0]), "+f"(c[1]), "+f"(c[2]), "+f"(c[3])
        : "r"(a0), "r"(a1), "r"(a2), "r"(a3), "r"(b0), "r"(b1));
}
// round-to-nearest fp32 -> tf32 (low 13 bits zeroed, correctly rounded)
static __forceinline__ __device__ uint32_t f2tf(float f) {
    uint32_t r;
    asm("cvt.rna.tf32.f32 %0, %1;" : "=r"(r) : "f"(f));
    return r;
}
static __forceinline__ __device__ bool lt(float v1, int i1, float v2, int i2) {
    return v1 < v2 || (v1 == v2 && i1 < i2);
}

__global__ __launch_bounds__(256, 2) void vq_kernel(const float* __restrict__ x,
                                                    const float* __restrict__ cb,
                                                    float* __restrict__ out) {
    extern __shared__ float sm[];
    float* s_x  = sm + SF_X;
    float* s_bh = sm + SF_BH;
    float* s_bl = sm + SF_BL;
    float* s_hn = sm + SF_HN;
    int*   s_c1 = reinterpret_cast<int*>(sm + SF_C1);
    int*   s_c2 = reinterpret_cast<int*>(sm + SF_C2);
    float* s_rs = sm + SF_RS;
    int*   s_fin = reinterpret_cast<int*>(sm + SF_FIN);

    const int tid  = threadIdx.x;
    const int wid  = tid >> 5;
    const int lane = tid & 31;
    const int g    = lane >> 2;      // fragment row within group
    const int tig  = lane & 3;       // thread in group
    const int wrow = wid * 16;       // this warp's first row
    const int nbase = blockIdx.x * BM;
    const int b = nbase >> 10;
    const int p = nbase & 1023;
    const float* xin = x + b * (CDIM * HWDIM) + p;

    // ---- fill x tile (raw fp32) into s_x[kk][128], stride 132 ----
    #pragma unroll
    for (int i = 0; i < 8; ++i) {
        int e  = tid + i * 256;
        int kk = e >> 5;
        int r4 = e & 31;
        float4 v = *reinterpret_cast<const float4*>(xin + kk * HWDIM + r4 * 4);
        *reinterpret_cast<float4*>(s_x + kk * STX + r4 * 4) = v;
    }
    #pragma unroll
    for (int i = 0; i < 4; ++i) {
        int k = tid + i * 256;
        s_hn[k] = d_hn[k];
    }
    __syncthreads();

    // top-2 running state for rows wrow+g (slot 0) and wrow+g+8 (slot 1)
    float bv0 = 3.4e38f, sv0 = 3.4e38f, bv1 = 3.4e38f, sv1 = 3.4e38f;
    int   bi0 = 0, si0 = 0, bi1 = 0, si1 = 0;

    #pragma unroll 1
    for (int ch = 0; ch < NCHUNK; ++ch) {
        // ---- split-fill B chunk with rna tf32 splits ----
        #pragma unroll
        for (int i = 0; i < 4; ++i) {
            int e    = tid + i * 256;
            int code = e & 63;
            int kf4  = e >> 6;
            float4 v = __ldg(reinterpret_cast<const float4*>(
                cb + (ch * BN + code) * CDIM + kf4 * 4));
            float f;
            uint32_t h;
            f = v.x; h = f2tf(f);
            s_bh[(kf4 * 4 + 0) * STB + code] = __uint_as_float(h);
            s_bl[(kf4 * 4 + 0) * STB + code] = __uint_as_float(f2tf(f - __uint_as_float(h)));
            f = v.y; h = f2tf(f);
            s_bh[(kf4 * 4 + 1) * STB + code] = __uint_as_float(h);
            s_bl[(kf4 * 4 + 1) * STB + code] = __uint_as_float(f2tf(f - __uint_as_float(h)));
            f = v.z; h = f2tf(f);
            s_bh[(kf4 * 4 + 2) * STB + code] = __uint_as_float(h);
            s_bl[(kf4 * 4 + 2) * STB + code] = __uint_as_float(f2tf(f - __uint_as_float(h)));
            f = v.w; h = f2tf(f);
            s_bh[(kf4 * 4 + 3) * STB + code] = __uint_as_float(h);
            s_bl[(kf4 * 4 + 3) * STB + code] = __uint_as_float(f2tf(f - __uint_as_float(h)));
        }
        __syncthreads();

        float c[8][4];
        #pragma unroll
        for (int nt = 0; nt < 8; ++nt)
            #pragma unroll
            for (int j = 0; j < 4; ++j) c[nt][j] = 0.f;

        #pragma unroll
        for (int ks = 0; ks < 8; ++ks) {
            const float* ax = s_x + (ks * 8 + tig) * STX + wrow + g;
            float af0 = ax[0];
            float af1 = ax[8];
            float af2 = ax[4 * STX];
            float af3 = ax[4 * STX + 8];
            uint32_t ah0 = f2tf(af0), ah1 = f2tf(af1), ah2 = f2tf(af2), ah3 = f2tf(af3);
            uint32_t al0 = f2tf(af0 - __uint_as_float(ah0));
            uint32_t al1 = f2tf(af1 - __uint_as_float(ah1));
            uint32_t al2 = f2tf(af2 - __uint_as_float(ah2));
            uint32_t al3 = f2tf(af3 - __uint_as_float(ah3));

            const int rb = (ks * 8 + tig) * STB + g;
            #pragma unroll
            for (int nt = 0; nt < 8; ++nt) {
                uint32_t bh0 = __float_as_uint(s_bh[rb + nt * 8]);
                uint32_t bh1 = __float_as_uint(s_bh[rb + 4 * STB + nt * 8]);
                uint32_t bl0 = __float_as_uint(s_bl[rb + nt * 8]);
                uint32_t bl1 = __float_as_uint(s_bl[rb + 4 * STB + nt * 8]);
                mma8(c[nt], ah0, ah1, ah2, ah3, bh0, bh1);
                mma8(c[nt], ah0, ah1, ah2, ah3, bl0, bl1);
                mma8(c[nt], al0, al1, al2, al3, bh0, bh1);
            }
        }

        // ---- running top-2 (ascending col order -> first-min kept on ties) ----
        #pragma unroll
        for (int nt = 0; nt < 8; ++nt) {
            int col0 = ch * BN + nt * 8 + 2 * tig;
            float hn0 = s_hn[col0];
            float hn1 = s_hn[col0 + 1];
            float s00 = hn0 - c[nt][0];
            float s01 = hn1 - c[nt][1];
            float s10 = hn0 - c[nt][2];
            float s11 = hn1 - c[nt][3];
            if (s00 < bv0) { sv0 = bv0; si0 = bi0; bv0 = s00; bi0 = col0; }
            else if (s00 < sv0) { sv0 = s00; si0 = col0; }
            if (s01 < bv0) { sv0 = bv0; si0 = bi0; bv0 = s01; bi0 = col0 + 1; }
            else if (s01 < sv0) { sv0 = s01; si0 = col0 + 1; }
            if (s10 < bv1) { sv1 = bv1; si1 = bi1; bv1 = s10; bi1 = col0; }
            else if (s10 < sv1) { sv1 = s10; si1 = col0; }
            if (s11 < bv1) { sv1 = bv1; si1 = bi1; bv1 = s11; bi1 = col0 + 1; }
            else if (s11 < sv1) { sv1 = s11; si1 = col0 + 1; }
        }
        __syncthreads();
    }

    // ---- merge top-2 across the 4 lanes of each group ----
    #pragma unroll
    for (int off = 2; off > 0; off >>= 1) {
        float oB0 = __shfl_down_sync(0xffffffffu, bv0, off, 4);
        int   oBi0 = __shfl_down_sync(0xffffffffu, bi0, off, 4);
        float oS0 = __shfl_down_sync(0xffffffffu, sv0, off, 4);
        int   oSi0 = __shfl_down_sync(0xffffffffu, si0, off, 4);
        float oB1 = __shfl_down_sync(0xffffffffu, bv1, off, 4);
        int   oBi1 = __shfl_down_sync(0xffffffffu, bi1, off, 4);
        float oS1 = __shfl_down_sync(0xffffffffu, sv1, off, 4);
        int   oSi1 = __shfl_down_sync(0xffffffffu, si1, off, 4);
        if (lt(oB0, oBi0, bv0, bi0)) {
            if (lt(bv0, bi0, oS0, oSi0)) { sv0 = bv0; si0 = bi0; }
            else                         { sv0 = oS0; si0 = oSi0; }
            bv0 = oB0; bi0 = oBi0;
        } else if (lt(oB0, oBi0, sv0, si0)) { sv0 = oB0; si0 = oBi0; }
        if (lt(oB1, oBi1, bv1, bi1)) {
            if (lt(bv1, bi1, oS1, oSi1)) { sv1 = bv1; si1 = bi1; }
            else                         { sv1 = oS1; si1 = oSi1; }
            bv1 = oB1; bi1 = oBi1;
        } else if (lt(oB1, oBi1, sv1, si1)) { sv1 = oB1; si1 = oBi1; }
    }
    if (tig == 0) {
        s_c1[wrow + g]     = bi0;  s_c2[wrow + g]     = si0;
        s_c1[wrow + g + 8] = bi1;  s_c2[wrow + g + 8] = si1;
    }
    __syncthreads();

    // ---- exact fp32 refinement of the two candidates per row ----
    {
        int row  = tid >> 1;
        int cand = tid & 1;
        int idx  = cand ? s_c2[row] : s_c1[row];
        const float4* cr = reinterpret_cast<const float4*>(cb + idx * CDIM);
        float dot = 0.f;
        #pragma unroll
        for (int i = 0; i < 16; ++i) {
            float4 v = __ldg(&cr[i]);
            const float* xr = s_x + (i * 4) * STX + row;
            dot = fmaf(xr[0 * STX], v.x, dot);
            dot = fmaf(xr[1 * STX], v.y, dot);
            dot = fmaf(xr[2 * STX], v.z, dot);
            dot = fmaf(xr[3 * STX], v.w, dot);
        }
        s_rs[row * 2 + cand] = s_hn[idx] - dot;
    }
    __syncthreads();
    if (tid < 128) {
        int   i1 = s_c1[tid], i2 = s_c2[tid];
        float v1 = s_rs[tid * 2], v2 = s_rs[tid * 2 + 1];
        s_fin[tid] = lt(v2, i2, v1, i1) ? i2 : i1;
    }
    __syncthreads();

    // ---- epilogue: gather winning code vectors, NCHW coalesced float4 ----
    float* outp = out + b * (CDIM * HWDIM) + p;
    #pragma unroll
    for (int i = 0; i < 8; ++i) {
        int e   = tid + i * 256;
        int chn = e >> 5;
        int r4  = e & 31;
        int i0 = s_fin[r4 * 4 + 0];
        int i1 = s_fin[r4 * 4 + 1];
        int i2 = s_fin[r4 * 4 + 2];
        int i3 = s_fin[r4 * 4 + 3];
        float4 o;
        o.x = __ldg(&cb[i0 * CDIM + chn]);
        o.y = __ldg(&cb[i1 * CDIM + chn]);
        o.z = __ldg(&cb[i2 * CDIM + chn]);
        o.w = __ldg(&cb[i3 * CDIM + chn]);
        *reinterpret_cast<float4*>(outp + chn * HWDIM + r4 * 4) = o;
    }
}

extern "C" void kernel_launch(void* const* d_in, const int* in_sizes, int n_in,
                              void* d_out, int out_size) {
    const float* x  = (const float*)d_in[0];   // inputs  [64,64,32,32]
    const float* cb = (const float*)d_in[1];   // codebook [1024,64]
    float* out = (float*)d_out;
    cudaFuncSetAttribute(vq_kernel, cudaFuncAttributeMaxDynamicSharedMemorySize, SMEM_BYTES);
    hn_kernel<<<4, 256>>>(cb);
    vq_kernel<<<NBLOCKS, 256, SMEM_BYTES>>>(x, cb, out);
}